// round 1
// baseline (speedup 1.0000x reference)
#include <cuda_runtime.h>

#define Mv    32768
#define Ev    262144
#define RANKv 5
#define FILTv 32
#define FINv  32
#define NBv   8
#define VEC   256   // FIN * NB, per-vertex vector length

// ---- device scratch (static, allocation-free) ----
__device__ float g_Ta[(size_t)Mv * VEC];
__device__ float g_Tb[(size_t)Mv * VEC];
__device__ float g_Tc[(size_t)Mv * VEC];
__device__ int   g_cnt[Mv];
__device__ int   g_rowptr[Mv + 1];
__device__ int   g_pos[Ev];
__device__ int   g_scols[Ev];   // pre-scaled by VEC
__device__ float g_svals[Ev];

// ---------------- CSR build ----------------
__global__ void k_zero() {
    g_cnt[blockIdx.x * 256 + threadIdx.x] = 0;
}

__global__ void k_hist(const int* __restrict__ rows) {
    int e = blockIdx.x * 256 + threadIdx.x;
    g_pos[e] = atomicAdd(&g_cnt[rows[e]], 1);
}

// single-block exclusive scan of g_cnt[32768] -> g_rowptr
__global__ void k_scan() {
    __shared__ int part[1024];
    int t = threadIdx.x;
    int base = t * 32;
    int s = 0;
#pragma unroll
    for (int i = 0; i < 32; i++) s += g_cnt[base + i];
    part[t] = s;
    __syncthreads();
    for (int off = 1; off < 1024; off <<= 1) {
        int v = (t >= off) ? part[t - off] : 0;
        __syncthreads();
        part[t] += v;
        __syncthreads();
    }
    int excl = (t == 0) ? 0 : part[t - 1];
#pragma unroll
    for (int i = 0; i < 32; i++) {
        g_rowptr[base + i] = excl;
        excl += g_cnt[base + i];
    }
    if (t == 1023) g_rowptr[Mv] = Ev;
}

__global__ void k_scatter(const int* __restrict__ rows,
                          const int* __restrict__ cols,
                          const float* __restrict__ vals) {
    int e = blockIdx.x * 256 + threadIdx.x;
    int idx = g_rowptr[rows[e]] + g_pos[e];
    g_scols[idx] = cols[e] * VEC;
    g_svals[idx] = vals[e];
}

// ---------------- init: transpose x -> T0 layout, write k=0 contribution ----------------
// x: [NB, M, FIN] row-major. T layout: T[m][f*NBv + n].
// out[n][m][filt] = bias[filt] + sum_f T0[m,f,n] * W[f*RANK + 0][filt]
__global__ void k_init(const float* __restrict__ x,
                       const float* __restrict__ kern,
                       const float* __restrict__ bias,
                       float* __restrict__ out) {
    __shared__ float sh[VEC];
    __shared__ float shW[FINv * FILTv];
    int m = blockIdx.x, t = threadIdx.x;
    int n = t >> 5, f = t & 31;
    float v = x[((size_t)n * Mv + m) * FINv + f];
    sh[f * NBv + n] = v;
    for (int i = t; i < FINv * FILTv; i += 256) {
        int ff = i >> 5, fl = i & 31;
        shW[i] = kern[(ff * RANKv + 0) * FILTv + fl];
    }
    __syncthreads();
    g_Ta[(size_t)m * VEC + t] = sh[t];           // coalesced T0 store
    int filt = t & 31;
    float acc = bias[filt];
#pragma unroll
    for (int ff = 0; ff < FINv; ff++)
        acc += sh[ff * NBv + n] * shW[ff * FILTv + filt];
    out[((size_t)n * Mv + m) * FILTv + filt] = acc;
}

// ---------------- fused Chebyshev step ----------------
// T_k[m,:] = (isFirst ? 1 : 2) * sum_e val_e * Tprev[col_e,:]  (- Tpp[m,:] if !isFirst)
// plus out += T_k-contribution through kernel slice kidx.
__global__ void k_step(int prevIdx, int ppIdx, int curIdx,
                       const float* __restrict__ kern,
                       float* __restrict__ out,
                       int kidx, int isFirst) {
    __shared__ float shv[VEC];
    __shared__ float shW[FINv * FILTv];
    __shared__ int   shc[32];
    __shared__ float shs[32];

    float* bufs[3] = { g_Ta, g_Tb, g_Tc };
    const float* __restrict__ Tprev = bufs[prevIdx];
    const float* __restrict__ Tpp   = bufs[ppIdx];
    float* __restrict__ Tcur        = bufs[curIdx];

    int m = blockIdx.x, t = threadIdx.x;

    for (int i = t; i < FINv * FILTv; i += 256) {
        int ff = i >> 5, fl = i & 31;
        shW[i] = kern[(ff * RANKv + kidx) * FILTv + fl];
    }

    int start = g_rowptr[m], end = g_rowptr[m + 1];
    float acc = 0.f;
    for (int b = start; b < end; b += 32) {
        int cnt = min(32, end - b);
        __syncthreads();
        if (t < cnt) { shc[t] = g_scols[b + t]; shs[t] = g_svals[b + t]; }
        __syncthreads();
#pragma unroll 4
        for (int i = 0; i < cnt; i++)
            acc += shs[i] * Tprev[(size_t)shc[i] + t];   // coalesced 1KB gather
    }

    float val = isFirst ? acc : (2.f * acc - Tpp[(size_t)m * VEC + t]);
    Tcur[(size_t)m * VEC + t] = val;
    __syncthreads();
    shv[t] = val;
    __syncthreads();

    int n = t >> 5, filt = t & 31;
    float o = 0.f;
#pragma unroll
    for (int ff = 0; ff < FINv; ff++)
        o += shv[ff * NBv + n] * shW[ff * FILTv + filt];   // broadcast + conflict-free
    size_t oi = ((size_t)n * Mv + m) * FILTv + filt;
    out[oi] += o;
}

extern "C" void kernel_launch(void* const* d_in, const int* in_sizes, int n_in,
                              void* d_out, int out_size) {
    const float* x    = (const float*)d_in[0];
    const float* vals = (const float*)d_in[1];
    const float* kern = (const float*)d_in[2];
    const float* bias = (const float*)d_in[3];
    const int*   rows = (const int*)  d_in[4];
    const int*   cols = (const int*)  d_in[5];
    float* out = (float*)d_out;

    // CSR build (per launch; deterministic set, cheap)
    k_zero   <<<Mv / 256, 256>>>();
    k_hist   <<<Ev / 256, 256>>>(rows);
    k_scan   <<<1, 1024>>>();
    k_scatter<<<Ev / 256, 256>>>(rows, cols, vals);

    // T0 transpose + k=0 output contribution (+bias)
    k_init<<<Mv, 256>>>(x, kern, bias, out);

    // T1..T4, each fused SpMM + recurrence + output contribution
    k_step<<<Mv, 256>>>(0, 0, 1, kern, out, 1, 1);  // T1 = L T0        (Ta -> Tb)
    k_step<<<Mv, 256>>>(1, 0, 2, kern, out, 2, 0);  // T2 = 2L T1 - T0  (-> Tc)
    k_step<<<Mv, 256>>>(2, 1, 0, kern, out, 3, 0);  // T3               (-> Ta)
    k_step<<<Mv, 256>>>(0, 2, 1, kern, out, 4, 0);  // T4               (-> Tb)
}

// round 2
// speedup vs baseline: 1.7342x; 1.7342x over previous
#include <cuda_runtime.h>

#define Mv    32768
#define Ev    262144
#define RANKv 5
#define FILTv 32
#define FINv  32
#define NBv   8
#define VEC   256   // FIN * NB

typedef unsigned long long u64;

__device__ float g_Ta[(size_t)Mv * VEC];
__device__ float g_Tb[(size_t)Mv * VEC];
__device__ float g_Tc[(size_t)Mv * VEC];
__device__ int   g_cnt[Mv];
__device__ int   g_rowptr[Mv + 1];
__device__ int   g_pos[Ev];
__device__ int   g_scols[Ev];   // pre-scaled by VEC
__device__ float g_svals[Ev];

// ---- packed f32x2 helpers ----
__device__ __forceinline__ u64 f2_pack(float lo, float hi) {
    u64 d; asm("mov.b64 %0, {%1, %2};" : "=l"(d) : "f"(lo), "f"(hi)); return d;
}
__device__ __forceinline__ void f2_unpack(u64 v, float& lo, float& hi) {
    asm("mov.b64 {%0, %1}, %2;" : "=f"(lo), "=f"(hi) : "l"(v));
}
__device__ __forceinline__ u64 f2_fma(u64 a, u64 b, u64 c) {
    u64 d; asm("fma.rn.f32x2 %0, %1, %2, %3;" : "=l"(d) : "l"(a), "l"(b), "l"(c)); return d;
}

// ---------------- CSR build ----------------
__global__ void k_zero() { g_cnt[blockIdx.x * 256 + threadIdx.x] = 0; }

__global__ void k_hist(const int* __restrict__ rows) {
    int e = blockIdx.x * 256 + threadIdx.x;
    g_pos[e] = atomicAdd(&g_cnt[rows[e]], 1);
}

__global__ void k_scan() {
    __shared__ int part[1024];
    int t = threadIdx.x;
    int base = t * 32;
    int s = 0;
#pragma unroll
    for (int i = 0; i < 32; i++) s += g_cnt[base + i];
    part[t] = s;
    __syncthreads();
    for (int off = 1; off < 1024; off <<= 1) {
        int v = (t >= off) ? part[t - off] : 0;
        __syncthreads();
        part[t] += v;
        __syncthreads();
    }
    int excl = (t == 0) ? 0 : part[t - 1];
#pragma unroll
    for (int i = 0; i < 32; i++) {
        g_rowptr[base + i] = excl;
        excl += g_cnt[base + i];
    }
    if (t == 1023) g_rowptr[Mv] = Ev;
}

__global__ void k_scatter(const int* __restrict__ rows,
                          const int* __restrict__ cols,
                          const float* __restrict__ vals) {
    int e = blockIdx.x * 256 + threadIdx.x;
    int idx = g_rowptr[rows[e]] + g_pos[e];
    g_scols[idx] = cols[e] * VEC;
    g_svals[idx] = vals[e];
}

// ---------------- shared GEMM epilogue ----------------
// shv[r][f*8+n] holds T_k for 4 rows; each thread: row r = t>>6, lane l = t&63,
// n = l>>3, filt-quad fb = (l&7)*4. acc init passed in (bias or out RMW).
__device__ __forceinline__ void gemm_epilogue(const float shv_r[VEC],
                                              const float* __restrict__ shW,
                                              int n, int fb,
                                              u64& a01, u64& a23) {
#pragma unroll
    for (int f = 0; f < FINv; f++) {
        float s = shv_r[f * NBv + n];
        u64 sd = f2_pack(s, s);
        float4 wv = *(const float4*)&shW[f * FILTv + fb];
        a01 = f2_fma(sd, f2_pack(wv.x, wv.y), a01);
        a23 = f2_fma(sd, f2_pack(wv.z, wv.w), a23);
    }
}

// ---------------- init: T0 + k=0 contribution + bias ----------------
__global__ void __launch_bounds__(256) k_init(const float* __restrict__ x,
                                              const float* __restrict__ kern,
                                              const float* __restrict__ bias,
                                              float* __restrict__ out) {
    __shared__ float shv[4][VEC];
    __shared__ float shW[FINv * FILTv];
    int t = threadIdx.x;
    int m0 = blockIdx.x * 4;
    int n8 = t >> 5, f = t & 31;
#pragma unroll
    for (int r = 0; r < 4; r++)
        shv[r][f * NBv + n8] = x[((size_t)n8 * Mv + (m0 + r)) * FINv + f];
    for (int i = t; i < FINv * FILTv; i += 256) {
        int ff = i >> 5, fl = i & 31;
        shW[i] = kern[(ff * RANKv + 0) * FILTv + fl];
    }
    __syncthreads();

    int r = t >> 6, l = t & 63;
    int m = m0 + r;
    *(float4*)&g_Ta[(size_t)m * VEC + 4 * l] = *(const float4*)&shv[r][4 * l];

    int n = l >> 3, fb = (l & 7) * 4;
    float4 bv = *(const float4*)&bias[fb];
    u64 a01 = f2_pack(bv.x, bv.y), a23 = f2_pack(bv.z, bv.w);
    gemm_epilogue(shv[r], shW, n, fb, a01, a23);
    float4 o;
    f2_unpack(a01, o.x, o.y);
    f2_unpack(a23, o.z, o.w);
    *(float4*)&out[((size_t)n * Mv + m) * FILTv + fb] = o;
}

// ---------------- fused Chebyshev step ----------------
__global__ void __launch_bounds__(256) k_step(int prevIdx, int ppIdx, int curIdx,
                                              const float* __restrict__ kern,
                                              float* __restrict__ out,
                                              int kidx, int isFirst, int writeT) {
    __shared__ float shv[4][VEC];
    __shared__ float shW[FINv * FILTv];

    float* bufs[3] = { g_Ta, g_Tb, g_Tc };
    const float* __restrict__ Tprev = bufs[prevIdx];
    const float* __restrict__ Tpp   = bufs[ppIdx];
    float* __restrict__ Tcur        = bufs[curIdx];

    int t = threadIdx.x;
    int r = t >> 6, l = t & 63;
    int m = blockIdx.x * 4 + r;

    for (int i = t; i < FINv * FILTv; i += 256) {
        int ff = i >> 5, fl = i & 31;
        shW[i] = kern[(ff * RANKv + kidx) * FILTv + fl];
    }

    int start = __ldg(&g_rowptr[m]), end = __ldg(&g_rowptr[m + 1]);
    u64 a0 = 0, a1 = 0;   // packed float4 accumulator
    for (int e = start; e < end; e++) {
        int c = __ldg(&g_scols[e]);
        float w = __ldg(&g_svals[e]);
        u64 wd = f2_pack(w, w);
        float4 v = *(const float4*)&Tprev[(size_t)c + 4 * l];
        a0 = f2_fma(wd, f2_pack(v.x, v.y), a0);
        a1 = f2_fma(wd, f2_pack(v.z, v.w), a1);
    }

    float4 val;
    f2_unpack(a0, val.x, val.y);
    f2_unpack(a1, val.z, val.w);
    if (!isFirst) {
        float4 p = *(const float4*)&Tpp[(size_t)m * VEC + 4 * l];
        val.x = 2.f * val.x - p.x;
        val.y = 2.f * val.y - p.y;
        val.z = 2.f * val.z - p.z;
        val.w = 2.f * val.w - p.w;
    }
    if (writeT)
        *(float4*)&Tcur[(size_t)m * VEC + 4 * l] = val;

    *(float4*)&shv[r][4 * l] = val;
    __syncthreads();

    int n = l >> 3, fb = (l & 7) * 4;
    size_t oi = ((size_t)n * Mv + m) * FILTv + fb;
    float4 ov = *(const float4*)&out[oi];          // RMW accumulate
    u64 a01 = f2_pack(ov.x, ov.y), a23 = f2_pack(ov.z, ov.w);
    gemm_epilogue(shv[r], shW, n, fb, a01, a23);
    float4 o;
    f2_unpack(a01, o.x, o.y);
    f2_unpack(a23, o.z, o.w);
    *(float4*)&out[oi] = o;
}

extern "C" void kernel_launch(void* const* d_in, const int* in_sizes, int n_in,
                              void* d_out, int out_size) {
    const float* x    = (const float*)d_in[0];
    const float* vals = (const float*)d_in[1];
    const float* kern = (const float*)d_in[2];
    const float* bias = (const float*)d_in[3];
    const int*   rows = (const int*)  d_in[4];
    const int*   cols = (const int*)  d_in[5];
    float* out = (float*)d_out;

    k_zero   <<<Mv / 256, 256>>>();
    k_hist   <<<Ev / 256, 256>>>(rows);
    k_scan   <<<1, 1024>>>();
    k_scatter<<<Ev / 256, 256>>>(rows, cols, vals);

    k_init<<<Mv / 4, 256>>>(x, kern, bias, out);

    k_step<<<Mv / 4, 256>>>(0, 0, 1, kern, out, 1, 1, 1);  // T1 = L T0       (Ta -> Tb)
    k_step<<<Mv / 4, 256>>>(1, 0, 2, kern, out, 2, 0, 1);  // T2 = 2L T1 - T0 (-> Tc)
    k_step<<<Mv / 4, 256>>>(2, 1, 0, kern, out, 3, 0, 1);  // T3              (-> Ta)
    k_step<<<Mv / 4, 256>>>(0, 2, 1, kern, out, 4, 0, 0);  // T4 (no store)
}